// round 4
// baseline (speedup 1.0000x reference)
#include <cuda_runtime.h>
#include <math.h>

#define T_SNAP 4
#define EQ     4096
#define NNODES 8192
#define H      32
#define BCAP   32                // in-edge bucket capacity per (t, node)
#define RCAP   128               // per-query reach-set capacity
#define HT     16384             // hash table slots (power of 2)
#define NB     (EQ * 3)          // pooled nodes (GRU batch)

#define GRID1  64                // L1: 64 blocks x 256 thr = 16384
#define BLK1   256
#define GRID2  208               // L2: 208 blocks x 128 thr = 26624
#define BLK2   128
#define NTH2   (GRID2 * BLK2)
#define NWARP2 (GRID2 * (BLK2 / 32))

// Scratch (static device globals, zero-initialized; every call restores zeros)
__device__ int    g_bcnt[T_SNAP * NNODES];
__device__ int    g_bsrc[T_SNAP * NNODES * BCAP];
__device__ float  g_tops[T_SNAP * EQ * 3];
__device__ int    g_htkey[HT];           // 0 = empty
__device__ float4 g_slotv[HT];
__device__ int    g_head[HT];            // per-slot list head (b+1; 0 = end)
__device__ int    g_next[NB];
__device__ int    g_uniq[NB];
__device__ int    g_uniq_cnt;
__device__ int    g_bar1, g_bar2;        // grid barrier counters (cross-reset)

__device__ __forceinline__ void grid_barrier(int* bar, int target) {
    __syncthreads();
    if (threadIdx.x == 0) {
        __threadfence();
        atomicAdd(bar, 1);
        while (atomicAdd(bar, 0) < target) {}
        __threadfence();
    }
    __syncthreads();
}

// helpers -------------------------------------------------------------------
__device__ __forceinline__ bool in_list(const int* l, int n, int x) {
    for (int i = 0; i < n; i++)
        if (l[i] == x) return true;
    return false;
}

// 2-hop backward BFS from seed within snapshot t; returns set size
__device__ __forceinline__ int bfs2(int t, int seed, int* R) {
    R[0] = seed;
    int n = 1, s = 0, e = 1;
#pragma unroll
    for (int hop = 0; hop < 2; hop++) {
        for (int i = s; i < e; i++) {
            int node = R[i];
            int c = g_bcnt[t * NNODES + node];
            if (c > BCAP) c = BCAP;
            const int* b = &g_bsrc[(t * NNODES + node) * BCAP];
            for (int j = 0; j < c; j++) {
                int src = b[j];
                if (!in_list(R, n, src) && n < RCAP) R[n++] = src;
            }
        }
        s = e; e = n;
    }
    return n;
}

// ---------------------------------------------------------------------------
// L1: scatter edges into buckets -> grid barrier -> per-(t,q) query + top-3
__global__ void __launch_bounds__(BLK1)
k_graph(const int* __restrict__ ei) {
    int idx = blockIdx.x * BLK1 + threadIdx.x;

    if (idx == 0) { g_uniq_cnt = 0; g_bar2 = 0; }   // resets for L2 / this call

    // ---- phase A: scatter (t, e) -> bucket of srcs at dst ----
    {
        int t = idx >> 12;                 // EQ = 4096
        int e = idx & (EQ - 1);
        int src = __ldg(&ei[t * 2 * EQ + e]);
        int dst = __ldg(&ei[t * 2 * EQ + EQ + e]);
        int pos = atomicAdd(&g_bcnt[t * NNODES + dst], 1);
        if (pos < BCAP) g_bsrc[(t * NNODES + dst) * BCAP + pos] = src;
    }

    grid_barrier(&g_bar1, GRID1);

    // ---- phase B: per-(t, q) reach sets, merged-subgraph in-degrees, top-3
    {
        int t = idx >> 12;
        int q = idx & (EQ - 1);
        int u = __ldg(&ei[(T_SNAP - 1) * 2 * EQ + q]);
        int v = __ldg(&ei[(T_SNAP - 1) * 2 * EQ + EQ + q]);

        int Ru[RCAP], Rv[RCAP];
        int nu = bfs2(t, u, Ru);
        int nv = bfs2(t, v, Rv);

        float t0 = 0.f, t1 = 0.f, t2 = 0.f;
        for (int pass = 0; pass < 2; pass++) {
            const int* L = pass ? Rv : Ru;
            int nL = pass ? nv : nu;
            for (int i = 0; i < nL; i++) {
                int node = L[i];
                bool inRu, inRv;
                if (pass == 0) {
                    inRu = true;
                    inRv = in_list(Rv, nv, node);
                } else {
                    inRu = in_list(Ru, nu, node);
                    if (inRu) continue;        // handled in pass 0
                    inRv = true;
                }
                int c = g_bcnt[t * NNODES + node];
                if (c > BCAP) c = BCAP;
                const int* b = &g_bsrc[(t * NNODES + node) * BCAP];
                int d = 0;
                for (int j = 0; j < c; j++) {
                    int src = b[j];
                    bool su = inRu && in_list(Ru, nu, src);
                    bool sv = inRv && in_list(Rv, nv, src);
                    if (su || sv) d++;
                }
                float f = (float)d;
                if (f > t0)      { t2 = t1; t1 = t0; t0 = f; }
                else if (f > t1) { t2 = t1; t1 = f; }
                else if (f > t2) { t2 = f; }
            }
        }
        g_tops[idx * 3 + 0] = t0;
        g_tops[idx * 3 + 1] = t1;
        g_tops[idx * 3 + 2] = t2;
    }
}

// ---------------------------------------------------------------------------
// L2: hash-dedup trajectories -> grid barrier -> GRU per unique + scatter-out
__global__ void __launch_bounds__(BLK2)
k_rnn(const float* __restrict__ Wg,  const float* __restrict__ bg,
      const float* __restrict__ Wih, const float* __restrict__ Whh,
      const float* __restrict__ bih, const float* __restrict__ bhh,
      float* __restrict__ out) {
    __shared__ float sWihT[H][3 * H];   // [kk][j], conflict-free
    __shared__ float sWhhT[H][3 * H];
    __shared__ float sbih[3 * H], sbhh[3 * H], sWg[H], sbg[H];

    int tid = threadIdx.x;
    int idx = blockIdx.x * BLK2 + tid;

    if (idx == 0) g_bar1 = 0;           // reset L1 barrier for next call

    for (int i = tid; i < 3 * H * H; i += BLK2) {
        int j = i / H, kk = i - j * H;
        sWihT[kk][j] = Wih[i];
        sWhhT[kk][j] = Whh[i];
    }
    for (int i = tid; i < 3 * H; i += BLK2) { sbih[i] = bih[i]; sbhh[i] = bhh[i]; }
    if (tid < H) { sWg[tid] = Wg[tid]; sbg[tid] = bg[tid]; }

    // ---- phase A: dedup degree 4-tuples, build per-slot inverse lists ----
    if (idx < NB) {
        int b = idx;
        int q = b / 3, p = b - q * 3;
        float v0 = g_tops[(0 * EQ + q) * 3 + p];
        float v1 = g_tops[(1 * EQ + q) * 3 + p];
        float v2 = g_tops[(2 * EQ + q) * 3 + p];
        float v3 = g_tops[(3 * EQ + q) * 3 + p];
        int i0 = (int)v0, i1 = (int)v1, i2 = (int)v2, i3 = (int)v3;
        int key;
        if (i0 > 254 || i1 > 254 || i2 > 254 || i3 > 254)
            key = (int)(0x80000000u | (unsigned)b);        // unique-self
        else
            key = i0 | (i1 << 8) | (i2 << 16) | (i3 << 24) | 0x40000000;
        unsigned hsl = ((unsigned)key * 2654435761u) & (HT - 1);
        int slot;
        for (;;) {
            int old = atomicCAS(&g_htkey[hsl], 0, key);
            if (old == 0) {
                g_slotv[hsl] = make_float4(v0, v1, v2, v3);
                int u = atomicAdd(&g_uniq_cnt, 1);
                g_uniq[u] = (int)hsl;
                slot = (int)hsl;
                break;
            }
            if (old == key) { slot = (int)hsl; break; }
            hsl = (hsl + 1) & (HT - 1);
        }
        g_next[b] = atomicExch(&g_head[slot], b + 1);
    }

    grid_barrier(&g_bar2, GRID2);

    // ---- phase B1: clear bucket counters for next call (unused here) ----
    for (int i = idx; i < T_SNAP * NNODES; i += NTH2) g_bcnt[i] = 0;

    // ---- phase B2: GRU per unique trajectory (one warp each) ----
    int cnt = g_uniq_cnt;
    int lane = tid & 31;
    int w = blockIdx.x * (BLK2 / 32) + (tid >> 5);
    for (int wg = w; wg < cnt; wg += NWARP2) {
        int slot = g_uniq[wg];
        float4 vv = g_slotv[slot];
        float vs[4] = {vv.x, vv.y, vv.z, vv.w};

        float h = 0.f;
#pragma unroll
        for (int t = 0; t < T_SNAP; t++) {
            float vt = vs[t];
            float x = fmaxf(vt * sWg[lane] + sbg[lane], 0.f);
            float gr = sbih[lane], gz = sbih[H + lane], gg = sbih[2 * H + lane];
            float hr = sbhh[lane], hz = sbhh[H + lane], hg = sbhh[2 * H + lane];
#pragma unroll
            for (int kk = 0; kk < H; kk++) {
                float xk = __shfl_sync(0xffffffffu, x, kk);
                float hk = __shfl_sync(0xffffffffu, h, kk);
                gr += sWihT[kk][lane]         * xk;
                gz += sWihT[kk][H + lane]     * xk;
                gg += sWihT[kk][2 * H + lane] * xk;
                hr += sWhhT[kk][lane]         * hk;
                hz += sWhhT[kk][H + lane]     * hk;
                hg += sWhhT[kk][2 * H + lane] * hk;
            }
            float r = 1.f / (1.f + expf(-(gr + hr)));
            float z = 1.f / (1.f + expf(-(gz + hz)));
            float n = tanhf(gg + r * hg);
            h = (1.f - z) * n + z * h;
        }

        // scatter h to every pooled node in this slot's list; reset slot state
        int cur;
        if (lane == 0) cur = g_head[slot];
        cur = __shfl_sync(0xffffffffu, cur, 0);
        while (cur) {
            int b = cur - 1;
            out[b * H + lane] = h;
            if (lane == 0) cur = g_next[b];
            cur = __shfl_sync(0xffffffffu, cur, 0);
        }
        if (lane == 0) { g_htkey[slot] = 0; g_head[slot] = 0; }
    }
}

// ---------------------------------------------------------------------------
extern "C" void kernel_launch(void* const* d_in, const int* in_sizes, int n_in,
                              void* d_out, int out_size) {
    const int*   ei  = (const int*)d_in[0];
    const float* Wg  = (const float*)d_in[1];
    const float* bg  = (const float*)d_in[2];
    const float* Wih = (const float*)d_in[3];
    const float* Whh = (const float*)d_in[4];
    const float* bih = (const float*)d_in[5];
    const float* bhh = (const float*)d_in[6];
    float* out = (float*)d_out;

    k_graph<<<GRID1, BLK1>>>(ei);
    k_rnn  <<<GRID2, BLK2>>>(Wg, bg, Wih, Whh, bih, bhh, out);
}

// round 5
// speedup vs baseline: 5.2224x; 5.2224x over previous
#include <cuda_runtime.h>
#include <math.h>

#define T_SNAP 4
#define EQ     4096
#define NNODES 8192
#define H      32
#define BCAP   32                // in-edge bucket capacity per (t, node)
#define RCAP   128               // per-query reach-set capacity
#define HT     16384             // hash table slots (power of 2)
#define NB     (EQ * 3)          // pooled nodes (GRU batch)

#define GRID1  64                // L1: 64 blocks x 256 thr = 16384
#define BLK1   256
#define GRID2  208               // L2: 208 blocks x 128 thr = 26624 (all-resident)
#define BLK2   128
#define NTH2   (GRID2 * BLK2)
#define NWARP2 (GRID2 * (BLK2 / 32))

// Scratch (static device globals, zero-initialized; every call restores zeros)
__device__ int    g_bcnt[T_SNAP * NNODES];
__device__ int    g_bsrc[T_SNAP * NNODES * BCAP];
__device__ float  g_tops[T_SNAP * EQ * 3];
__device__ int    g_htkey[HT];           // 0 = empty
__device__ float4 g_slotv[HT];
__device__ float  g_uh[HT * H];
__device__ int    g_bslot[NB];
__device__ int    g_uniq[NB];
__device__ int    g_uniq_cnt;
__device__ int    g_bar1, g_bar2, g_bar3;  // grid barrier counters (cross-reset)

__device__ __forceinline__ void grid_barrier(int* bar, int target) {
    __syncthreads();
    if (threadIdx.x == 0) {
        __threadfence();
        atomicAdd(bar, 1);
        while (atomicAdd(bar, 0) < target) {}
        __threadfence();
    }
    __syncthreads();
}

// helpers -------------------------------------------------------------------
__device__ __forceinline__ bool in_list(const int* l, int n, int x) {
    for (int i = 0; i < n; i++)
        if (l[i] == x) return true;
    return false;
}

// 2-hop backward BFS from seed within snapshot t; returns set size
__device__ __forceinline__ int bfs2(int t, int seed, int* R) {
    R[0] = seed;
    int n = 1, s = 0, e = 1;
#pragma unroll
    for (int hop = 0; hop < 2; hop++) {
        for (int i = s; i < e; i++) {
            int node = R[i];
            int c = g_bcnt[t * NNODES + node];
            if (c > BCAP) c = BCAP;
            const int* b = &g_bsrc[(t * NNODES + node) * BCAP];
            for (int j = 0; j < c; j++) {
                int src = b[j];
                if (!in_list(R, n, src) && n < RCAP) R[n++] = src;
            }
        }
        s = e; e = n;
    }
    return n;
}

// ---------------------------------------------------------------------------
// L1: scatter edges into buckets -> grid barrier -> per-(t,q) query + top-3
__global__ void __launch_bounds__(BLK1)
k_graph(const int* __restrict__ ei) {
    int idx = blockIdx.x * BLK1 + threadIdx.x;

    if (idx == 0) { g_uniq_cnt = 0; g_bar2 = 0; g_bar3 = 0; }  // resets for L2

    // ---- phase A: scatter (t, e) -> bucket of srcs at dst ----
    {
        int t = idx >> 12;                 // EQ = 4096
        int e = idx & (EQ - 1);
        int src = __ldg(&ei[t * 2 * EQ + e]);
        int dst = __ldg(&ei[t * 2 * EQ + EQ + e]);
        int pos = atomicAdd(&g_bcnt[t * NNODES + dst], 1);
        if (pos < BCAP) g_bsrc[(t * NNODES + dst) * BCAP + pos] = src;
    }

    grid_barrier(&g_bar1, GRID1);

    // ---- phase B: per-(t, q) reach sets, merged-subgraph in-degrees, top-3
    {
        int t = idx >> 12;
        int q = idx & (EQ - 1);
        int u = __ldg(&ei[(T_SNAP - 1) * 2 * EQ + q]);
        int v = __ldg(&ei[(T_SNAP - 1) * 2 * EQ + EQ + q]);

        int Ru[RCAP], Rv[RCAP];
        int nu = bfs2(t, u, Ru);
        int nv = bfs2(t, v, Rv);

        float t0 = 0.f, t1 = 0.f, t2 = 0.f;
        for (int pass = 0; pass < 2; pass++) {
            const int* L = pass ? Rv : Ru;
            int nL = pass ? nv : nu;
            for (int i = 0; i < nL; i++) {
                int node = L[i];
                bool inRu, inRv;
                if (pass == 0) {
                    inRu = true;
                    inRv = in_list(Rv, nv, node);
                } else {
                    inRu = in_list(Ru, nu, node);
                    if (inRu) continue;        // handled in pass 0
                    inRv = true;
                }
                int c = g_bcnt[t * NNODES + node];
                if (c > BCAP) c = BCAP;
                const int* b = &g_bsrc[(t * NNODES + node) * BCAP];
                int d = 0;
                for (int j = 0; j < c; j++) {
                    int src = b[j];
                    bool su = inRu && in_list(Ru, nu, src);
                    bool sv = inRv && in_list(Rv, nv, src);
                    if (su || sv) d++;
                }
                float f = (float)d;
                if (f > t0)      { t2 = t1; t1 = t0; t0 = f; }
                else if (f > t1) { t2 = t1; t1 = f; }
                else if (f > t2) { t2 = f; }
            }
        }
        g_tops[idx * 3 + 0] = t0;
        g_tops[idx * 3 + 1] = t1;
        g_tops[idx * 3 + 2] = t2;
    }
}

// ---------------------------------------------------------------------------
// L2: hash-dedup -> barrier -> GRU per unique -> barrier -> parallel gather
__global__ void __launch_bounds__(BLK2)
k_rnn(const float* __restrict__ Wg,  const float* __restrict__ bg,
      const float* __restrict__ Wih, const float* __restrict__ Whh,
      const float* __restrict__ bih, const float* __restrict__ bhh,
      float* __restrict__ out) {
    __shared__ float sWihT[H][3 * H];   // [kk][j], conflict-free
    __shared__ float sWhhT[H][3 * H];
    __shared__ float sbih[3 * H], sbhh[3 * H], sWg[H], sbg[H];

    int tid = threadIdx.x;
    int idx = blockIdx.x * BLK2 + tid;

    if (idx == 0) g_bar1 = 0;           // reset L1 barrier for next call

    for (int i = tid; i < 3 * H * H; i += BLK2) {
        int j = i / H, kk = i - j * H;
        sWihT[kk][j] = Wih[i];
        sWhhT[kk][j] = Whh[i];
    }
    for (int i = tid; i < 3 * H; i += BLK2) { sbih[i] = bih[i]; sbhh[i] = bhh[i]; }
    if (tid < H) { sWg[tid] = Wg[tid]; sbg[tid] = bg[tid]; }

    // ---- phase A: dedup degree 4-tuples via hash table, record slot per b ----
    if (idx < NB) {
        int b = idx;
        int q = b / 3, p = b - q * 3;
        float v0 = g_tops[(0 * EQ + q) * 3 + p];
        float v1 = g_tops[(1 * EQ + q) * 3 + p];
        float v2 = g_tops[(2 * EQ + q) * 3 + p];
        float v3 = g_tops[(3 * EQ + q) * 3 + p];
        int i0 = (int)v0, i1 = (int)v1, i2 = (int)v2, i3 = (int)v3;
        int key;
        if (i0 > 254 || i1 > 254 || i2 > 254 || i3 > 254)
            key = (int)(0x80000000u | (unsigned)b);        // unique-self
        else
            key = i0 | (i1 << 8) | (i2 << 16) | (i3 << 24) | 0x40000000;
        unsigned hsl = ((unsigned)key * 2654435761u) & (HT - 1);
        int slot;
        for (;;) {
            int old = atomicCAS(&g_htkey[hsl], 0, key);
            if (old == 0) {
                g_slotv[hsl] = make_float4(v0, v1, v2, v3);
                int u = atomicAdd(&g_uniq_cnt, 1);
                g_uniq[u] = (int)hsl;
                slot = (int)hsl;
                break;
            }
            if (old == key) { slot = (int)hsl; break; }
            hsl = (hsl + 1) & (HT - 1);
        }
        g_bslot[b] = slot;
    }

    grid_barrier(&g_bar2, GRID2);

    // ---- phase B1: clear bucket counters for next call (consumed already) ----
    for (int i = idx; i < T_SNAP * NNODES; i += NTH2) g_bcnt[i] = 0;

    // ---- phase B2: GRU per unique trajectory (one warp each) ----
    int cnt = g_uniq_cnt;
    int lane = tid & 31;
    int w = blockIdx.x * (BLK2 / 32) + (tid >> 5);
    for (int wg = w; wg < cnt; wg += NWARP2) {
        int slot = g_uniq[wg];
        float4 vv = g_slotv[slot];
        float vs[4] = {vv.x, vv.y, vv.z, vv.w};

        float h = 0.f;
#pragma unroll
        for (int t = 0; t < T_SNAP; t++) {
            float vt = vs[t];
            float x = fmaxf(vt * sWg[lane] + sbg[lane], 0.f);
            float gr = sbih[lane], gz = sbih[H + lane], gg = sbih[2 * H + lane];
            float hr = sbhh[lane], hz = sbhh[H + lane], hg = sbhh[2 * H + lane];
#pragma unroll
            for (int kk = 0; kk < H; kk++) {
                float xk = __shfl_sync(0xffffffffu, x, kk);
                float hk = __shfl_sync(0xffffffffu, h, kk);
                gr += sWihT[kk][lane]         * xk;
                gz += sWihT[kk][H + lane]     * xk;
                gg += sWihT[kk][2 * H + lane] * xk;
                hr += sWhhT[kk][lane]         * hk;
                hz += sWhhT[kk][H + lane]     * hk;
                hg += sWhhT[kk][2 * H + lane] * hk;
            }
            float r = 1.f / (1.f + expf(-(gr + hr)));
            float z = 1.f / (1.f + expf(-(gz + hz)));
            float n = tanhf(gg + r * hg);
            h = (1.f - z) * n + z * h;
        }
        g_uh[slot * H + lane] = h;
        if (lane == 0) g_htkey[slot] = 0;   // reset for next call
    }

    grid_barrier(&g_bar3, GRID2);

    // ---- phase C: parallel coalesced gather to output ----
    for (int i = idx; i < NB * H; i += NTH2) {
        int b = i >> 5;
        int j = i & (H - 1);
        out[i] = g_uh[g_bslot[b] * H + j];
    }
}

// ---------------------------------------------------------------------------
extern "C" void kernel_launch(void* const* d_in, const int* in_sizes, int n_in,
                              void* d_out, int out_size) {
    const int*   ei  = (const int*)d_in[0];
    const float* Wg  = (const float*)d_in[1];
    const float* bg  = (const float*)d_in[2];
    const float* Wih = (const float*)d_in[3];
    const float* Whh = (const float*)d_in[4];
    const float* bih = (const float*)d_in[5];
    const float* bhh = (const float*)d_in[6];
    float* out = (float*)d_out;

    k_graph<<<GRID1, BLK1>>>(ei);
    k_rnn  <<<GRID2, BLK2>>>(Wg, bg, Wih, Whh, bih, bhh, out);
}

// round 6
// speedup vs baseline: 5.4298x; 1.0397x over previous
#include <cuda_runtime.h>
#include <math.h>

#define T_SNAP 4
#define EQ     4096
#define NNODES 8192
#define H      32
#define BCAP   32                // in-edge bucket capacity per (t, node)
#define RCAP   128               // per-query reach-set capacity
#define HT     16384             // hash table slots (power of 2)
#define NB     (EQ * 3)          // pooled nodes (GRU batch)

#define GRID1  128               // L1: 128 blocks x 128 thr = 16384
#define BLK1   128
#define GRID2  296               // L2: 296 blocks x 128 thr (2/SM, all-resident)
#define BLK2   128
#define NTH2   (GRID2 * BLK2)
#define NWARP2 (GRID2 * (BLK2 / 32))

// Scratch (static device globals, zero-initialized; every call restores zeros)
__device__ int    g_bcnt[T_SNAP * NNODES];
__device__ int    g_bsrc[T_SNAP * NNODES * BCAP];
__device__ float  g_tops[T_SNAP * EQ * 3];
__device__ float  g_gi[256 * 3 * H];       // gi(v): 256 degrees x (3H), bih folded in
__device__ int    g_htkey[HT];             // 0 = empty
__device__ float4 g_slotv[HT];
__device__ float  g_uh[HT * H];
__device__ int    g_bslot[NB];
__device__ int    g_uniq[NB];
__device__ int    g_uniq_cnt;
__device__ int    g_bar1, g_bar2, g_bar3;  // grid barrier counters (cross-reset)

__device__ __forceinline__ void grid_barrier(int* bar, int target) {
    __syncthreads();
    if (threadIdx.x == 0) {
        __threadfence();
        atomicAdd(bar, 1);
        while (atomicAdd(bar, 0) < target) {}
        __threadfence();
    }
    __syncthreads();
}

__device__ __forceinline__ float fast_sigmoid(float x) {
    return 1.f / (1.f + __expf(-x));
}
__device__ __forceinline__ float fast_tanh(float x) {
    return 2.f / (1.f + __expf(-2.f * x)) - 1.f;
}

// helpers -------------------------------------------------------------------
__device__ __forceinline__ bool in_list(const int* l, int n, int x) {
    for (int i = 0; i < n; i++)
        if (l[i] == x) return true;
    return false;
}

// 2-hop backward BFS from seed within snapshot t; returns set size
__device__ __forceinline__ int bfs2(int t, int seed, int* R) {
    R[0] = seed;
    int n = 1, s = 0, e = 1;
#pragma unroll
    for (int hop = 0; hop < 2; hop++) {
        for (int i = s; i < e; i++) {
            int node = R[i];
            int c = g_bcnt[t * NNODES + node];
            if (c > BCAP) c = BCAP;
            const int* b = &g_bsrc[(t * NNODES + node) * BCAP];
            for (int j = 0; j < c; j++) {
                int src = b[j];
                if (!in_list(R, n, src) && n < RCAP) R[n++] = src;
            }
        }
        s = e; e = n;
    }
    return n;
}

// ---------------------------------------------------------------------------
// L1: scatter edges into buckets -> grid barrier -> per-(t,q) query + top-3
__global__ void __launch_bounds__(BLK1)
k_graph(const int* __restrict__ ei) {
    int idx = blockIdx.x * BLK1 + threadIdx.x;

    if (idx == 0) { g_uniq_cnt = 0; g_bar2 = 0; g_bar3 = 0; }  // resets for L2

    // ---- phase A: scatter (t, e) -> bucket of srcs at dst ----
    {
        int t = idx >> 12;                 // EQ = 4096
        int e = idx & (EQ - 1);
        int src = __ldg(&ei[t * 2 * EQ + e]);
        int dst = __ldg(&ei[t * 2 * EQ + EQ + e]);
        int pos = atomicAdd(&g_bcnt[t * NNODES + dst], 1);
        if (pos < BCAP) g_bsrc[(t * NNODES + dst) * BCAP + pos] = src;
    }

    grid_barrier(&g_bar1, GRID1);

    // ---- phase B: per-(t, q) reach sets, merged-subgraph in-degrees, top-3
    {
        int t = idx >> 12;
        int q = idx & (EQ - 1);
        int u = __ldg(&ei[(T_SNAP - 1) * 2 * EQ + q]);
        int v = __ldg(&ei[(T_SNAP - 1) * 2 * EQ + EQ + q]);

        int Ru[RCAP], Rv[RCAP];
        int nu = bfs2(t, u, Ru);
        int nv = bfs2(t, v, Rv);

        float t0 = 0.f, t1 = 0.f, t2 = 0.f;
        for (int pass = 0; pass < 2; pass++) {
            const int* L = pass ? Rv : Ru;
            int nL = pass ? nv : nu;
            for (int i = 0; i < nL; i++) {
                int node = L[i];
                bool inRu, inRv;
                if (pass == 0) {
                    inRu = true;
                    inRv = in_list(Rv, nv, node);
                } else {
                    inRu = in_list(Ru, nu, node);
                    if (inRu) continue;        // handled in pass 0
                    inRv = true;
                }
                int c = g_bcnt[t * NNODES + node];
                if (c > BCAP) c = BCAP;
                const int* b = &g_bsrc[(t * NNODES + node) * BCAP];
                int d = 0;
                for (int j = 0; j < c; j++) {
                    int src = b[j];
                    bool su = inRu && in_list(Ru, nu, src);
                    bool sv = inRv && in_list(Rv, nv, src);
                    if (su || sv) d++;
                }
                float f = (float)d;
                if (f > t0)      { t2 = t1; t1 = t0; t0 = f; }
                else if (f > t1) { t2 = t1; t1 = f; }
                else if (f > t2) { t2 = f; }
            }
        }
        g_tops[idx * 3 + 0] = t0;
        g_tops[idx * 3 + 1] = t1;
        g_tops[idx * 3 + 2] = t2;
    }
}

// ---------------------------------------------------------------------------
// L2: (gi table + hash-dedup) -> barrier -> GRU per unique -> barrier -> gather
__global__ void __launch_bounds__(BLK2, 2)
k_rnn(const float* __restrict__ Wg,  const float* __restrict__ bg,
      const float* __restrict__ Wih, const float* __restrict__ Whh,
      const float* __restrict__ bih, const float* __restrict__ bhh,
      float* __restrict__ out) {
    __shared__ float sWhhT[H][3 * H];   // [kk][j], conflict-free
    __shared__ float sbhh[3 * H];

    int tid = threadIdx.x;
    int idx = blockIdx.x * BLK2 + tid;

    if (idx == 0) g_bar1 = 0;           // reset L1 barrier for next call

    for (int i = tid; i < 3 * H * H; i += BLK2) {
        int j = i / H, kk = i - j * H;
        sWhhT[kk][j] = Whh[i];
    }
    if (tid < 3 * H) sbhh[tid] = bhh[tid];

    // ---- phase A1: gi(v) table, one entry per thread ----
    // gi[v*96 + j] = bih[j] + sum_k Wih[j,k] * relu(v*Wg[k] + bg[k])
    if (idx < 256 * 3 * H) {
        int v = idx / (3 * H);
        int j = idx - v * (3 * H);
        float acc = __ldg(&bih[j]);
        float fv = (float)v;
#pragma unroll
        for (int kk = 0; kk < H; kk++) {
            float xk = fmaxf(fv * __ldg(&Wg[kk]) + __ldg(&bg[kk]), 0.f);
            acc += __ldg(&Wih[j * H + kk]) * xk;
        }
        g_gi[idx] = acc;
    }

    // ---- phase A2: dedup degree 4-tuples, record slot per pooled node ----
    if (idx < NB) {
        int b = idx;
        int q = b / 3, p = b - q * 3;
        float v0 = g_tops[(0 * EQ + q) * 3 + p];
        float v1 = g_tops[(1 * EQ + q) * 3 + p];
        float v2 = g_tops[(2 * EQ + q) * 3 + p];
        float v3 = g_tops[(3 * EQ + q) * 3 + p];
        int i0 = (int)v0, i1 = (int)v1, i2 = (int)v2, i3 = (int)v3;
        int key;
        if (i0 > 254 || i1 > 254 || i2 > 254 || i3 > 254)
            key = (int)(0x80000000u | (unsigned)b);        // unique-self
        else
            key = i0 | (i1 << 8) | (i2 << 16) | (i3 << 24) | 0x40000000;
        unsigned hsl = ((unsigned)key * 2654435761u) & (HT - 1);
        int slot;
        for (;;) {
            int cur = ((volatile int*)g_htkey)[hsl];       // fast path: no atomic
            if (cur == key) { slot = (int)hsl; break; }
            if (cur == 0) {
                int old = atomicCAS(&g_htkey[hsl], 0, key);
                if (old == 0) {
                    g_slotv[hsl] = make_float4(v0, v1, v2, v3);
                    int u = atomicAdd(&g_uniq_cnt, 1);
                    g_uniq[u] = (int)hsl;
                    slot = (int)hsl;
                    break;
                }
                if (old == key) { slot = (int)hsl; break; }
            }
            hsl = (hsl + 1) & (HT - 1);
        }
        g_bslot[b] = slot;
    }

    grid_barrier(&g_bar2, GRID2);

    // ---- phase B1: clear bucket counters for next call (consumed already) ----
    for (int i = idx; i < T_SNAP * NNODES; i += NTH2) g_bcnt[i] = 0;

    // ---- phase B2: GRU per unique trajectory (one warp each) ----
    int cnt = g_uniq_cnt;
    int lane = tid & 31;
    int w = blockIdx.x * (BLK2 / 32) + (tid >> 5);
    for (int wg = w; wg < cnt; wg += NWARP2) {
        int slot = g_uniq[wg];
        float4 vv = g_slotv[slot];
        float vs[4] = {vv.x, vv.y, vv.z, vv.w};

        // prefetch input-side gates for all 4 steps (coalesced table reads)
        float pr[4], pz[4], pg[4];
#pragma unroll
        for (int t = 0; t < T_SNAP; t++) {
            int iv = (int)vs[t];
            if (iv >= 0 && iv < 256) {
                const float* gp = &g_gi[iv * 3 * H];
                pr[t] = gp[lane];
                pz[t] = gp[H + lane];
                pg[t] = gp[2 * H + lane];
            } else {   // rare exact fallback: compute from weights
                float x = fmaxf(vs[t] * __ldg(&Wg[lane]) + __ldg(&bg[lane]), 0.f);
                float ar = __ldg(&bih[lane]);
                float az = __ldg(&bih[H + lane]);
                float ag = __ldg(&bih[2 * H + lane]);
                for (int kk = 0; kk < H; kk++) {
                    float xk = __shfl_sync(0xffffffffu, x, kk);
                    ar += __ldg(&Wih[lane * H + kk]) * xk;
                    az += __ldg(&Wih[(H + lane) * H + kk]) * xk;
                    ag += __ldg(&Wih[(2 * H + lane) * H + kk]) * xk;
                }
                pr[t] = ar; pz[t] = az; pg[t] = ag;
            }
        }

        float h = 0.f;
#pragma unroll
        for (int t = 0; t < T_SNAP; t++) {
            float hr = sbhh[lane], hz = sbhh[H + lane], hg = sbhh[2 * H + lane];
#pragma unroll
            for (int kk = 0; kk < H; kk++) {
                float hk = __shfl_sync(0xffffffffu, h, kk);
                hr += sWhhT[kk][lane]         * hk;
                hz += sWhhT[kk][H + lane]     * hk;
                hg += sWhhT[kk][2 * H + lane] * hk;
            }
            float r = fast_sigmoid(pr[t] + hr);
            float z = fast_sigmoid(pz[t] + hz);
            float n = fast_tanh(pg[t] + r * hg);
            h = (1.f - z) * n + z * h;
        }
        g_uh[slot * H + lane] = h;
        if (lane == 0) g_htkey[slot] = 0;   // reset for next call
    }

    grid_barrier(&g_bar3, GRID2);

    // ---- phase C: parallel coalesced gather to output ----
    for (int i = idx; i < NB * H; i += NTH2) {
        int b = i >> 5;
        int j = i & (H - 1);
        out[i] = g_uh[g_bslot[b] * H + j];
    }
}

// ---------------------------------------------------------------------------
extern "C" void kernel_launch(void* const* d_in, const int* in_sizes, int n_in,
                              void* d_out, int out_size) {
    const int*   ei  = (const int*)d_in[0];
    const float* Wg  = (const float*)d_in[1];
    const float* bg  = (const float*)d_in[2];
    const float* Wih = (const float*)d_in[3];
    const float* Whh = (const float*)d_in[4];
    const float* bih = (const float*)d_in[5];
    const float* bhh = (const float*)d_in[6];
    float* out = (float*)d_out;

    k_graph<<<GRID1, BLK1>>>(ei);
    k_rnn  <<<GRID2, BLK2>>>(Wg, bg, Wih, Whh, bih, bhh, out);
}